// round 14
// baseline (speedup 1.0000x reference)
#include <cuda_runtime.h>
#include <cuda_bf16.h>
#include <float.h>
#include <math.h>

#define BV 128
#define BT 64
#define EMB 512
#define NP 196
#define NR 197
#define NKEEP 118
#define KP 58
#define HID 102
#define MAXKT 100
#define WCS 132
#define XSS 264

typedef unsigned long long ull;

__device__ float g_inv[BV * NR];
__device__ float g_self[BV * NP];
__device__ float g_logits[BV * KP * NP];               // transposed [b][p][j]
__device__ float g_capglo[BT * EMB];
__device__ float g_selcap[BT * 32 * EMB];
__device__ int   g_nt[BT];
__device__ float g_score[BT * BV * NP];
__device__ float g_imgr[(size_t)BV * NR * EMB];        // tf32-rounded rows
__device__ float g_Wc[(size_t)BT * BV * 58 * 120];     // compact kept weights (tf32)
__device__ int   g_kidx[BT * BV * 128];
__device__ int   g_nidx[BT * BV * 80];
__device__ float g_wnon[BT * BV * 80];
__device__ float g_S[(size_t)BT * BV * 2 * 32 * 64];
__device__ float g_N2[BT * BV * 2 * 64];
__device__ float g_lg[BT * 60 * 32];                   // caption word logits

__device__ __forceinline__ float gelu_f(float x) {
    return 0.5f * x * (1.0f + erff(x * 0.70710678118654752440f));
}
__device__ __forceinline__ ull pk2(float lo, float hi) {
    ull r; asm("mov.b64 %0,{%1,%2};" : "=l"(r) : "f"(lo), "f"(hi)); return r;
}
__device__ __forceinline__ void fma2(ull& a, ull x, ull w) {
    asm("fma.rn.f32x2 %0,%1,%2,%0;" : "+l"(a) : "l"(x), "l"(w));
}
__device__ __forceinline__ float2 upk2(ull a) {
    float lo, hi; asm("mov.b64 {%0,%1},%2;" : "=f"(lo), "=f"(hi) : "l"(a));
    return make_float2(lo, hi);
}
__device__ __forceinline__ unsigned f2k(float f) {
    unsigned u = __float_as_uint(f);
    return (u & 0x80000000u) ? ~u : (u | 0x80000000u);
}
__device__ __forceinline__ unsigned tf32r(float x) {
    unsigned r; asm("cvt.rna.tf32.f32 %0,%1;" : "=r"(r) : "f"(x)); return r;
}
__device__ __forceinline__ void mma8(float* d, unsigned a0, unsigned a1, unsigned a2,
                                     unsigned a3, unsigned b0, unsigned b1) {
    asm("mma.sync.aligned.m16n8k8.row.col.f32.tf32.tf32.f32 "
        "{%0,%1,%2,%3},{%4,%5,%6,%7},{%8,%9},{%0,%1,%2,%3};"
        : "+f"(d[0]), "+f"(d[1]), "+f"(d[2]), "+f"(d[3])
        : "r"(a0), "r"(a1), "r"(a2), "r"(a3), "r"(b0), "r"(b1));
}
__device__ __forceinline__ void cpa16(void* s, const void* g) {
    unsigned sa = (unsigned)__cvta_generic_to_shared(s);
    asm volatile("cp.async.cg.shared.global [%0], [%1], 16;" :: "r"(sa), "l"(g));
}

__device__ __forceinline__ float bsum(float v, float* buf) {
    for (int o = 16; o; o >>= 1) v += __shfl_down_sync(0xffffffffu, v, o);
    int w = threadIdx.x >> 5, l = threadIdx.x & 31;
    if (l == 0) buf[w] = v;
    __syncthreads();
    float r = (threadIdx.x < 8) ? buf[threadIdx.x] : 0.0f;
    if (w == 0) {
        for (int o = 4; o; o >>= 1) r += __shfl_down_sync(0xffffffffu, r, o);
        if (l == 0) buf[0] = r;
    }
    __syncthreads();
    float res = buf[0];
    __syncthreads();
    return res;
}

// ---------------- K0r ----------------
__global__ void __launch_bounds__(256) k0r(const float* __restrict__ img) {
    size_t total = (size_t)BV * NR * 128;
    for (size_t idx = (size_t)blockIdx.x * 256 + threadIdx.x; idx < total;
         idx += (size_t)gridDim.x * 256) {
        float4 v = *(const float4*)(img + idx * 4);
        v.x = __uint_as_float(tf32r(v.x));
        v.y = __uint_as_float(tf32r(v.y));
        v.z = __uint_as_float(tf32r(v.z));
        v.w = __uint_as_float(tf32r(v.w));
        *(float4*)(g_imgr + idx * 4) = v;
    }
}

// ---------------- K1 ----------------
__global__ void __launch_bounds__(256) k1_img(const float* __restrict__ img) {
    int b = blockIdx.x;
    const float* base = img + (size_t)b * NR * EMB;
    __shared__ float sm[EMB];
    __shared__ float red[32];
    int tid = threadIdx.x;
    for (int c = tid; c < EMB; c += 256) {
        float s = 0.f;
        for (int j = 1; j < NR; ++j) s += base[(size_t)j * EMB + c];
        sm[c] = s * (1.0f / NP);
    }
    __syncthreads();
    float pv = 0.f;
    for (int c = tid; c < EMB; c += 256) { float v = sm[c]; pv += v * v; }
    float nn = bsum(pv, red);
    float rn = 1.f / fmaxf(sqrtf(nn), 1e-12f);
    for (int c = tid; c < EMB; c += 256) sm[c] *= rn;
    __syncthreads();
    int wid = tid >> 5, lane = tid & 31;
    for (int j = wid; j < NR; j += 8) {
        const float* r = base + (size_t)j * EMB;
        float s2 = 0.f, sd = 0.f;
        for (int k = lane; k < EMB; k += 32) { float v = r[k]; s2 += v * v; sd += v * sm[k]; }
        for (int o = 16; o; o >>= 1) {
            s2 += __shfl_down_sync(0xffffffffu, s2, o);
            sd += __shfl_down_sync(0xffffffffu, sd, o);
        }
        if (lane == 0) {
            float inv = 1.f / fmaxf(sqrtf(s2), 1e-12f);
            g_inv[b * NR + j] = inv;
            if (j >= 1) g_self[b * NP + j - 1] = sd * inv;
        }
    }
}

// ---------------- K2: 512 threads, fused LN reduce, c-split matvec ----------------
__global__ void __launch_bounds__(512) k2_logits(
    const float* __restrict__ img,
    const float* __restrict__ lng, const float* __restrict__ lnb,
    const float* __restrict__ w1, const float* __restrict__ b1,
    const float* __restrict__ w2, const float* __restrict__ b2) {
    extern __shared__ float w1s[];    // 512*102
    __shared__ float ln[2][EMB];
    __shared__ float gh[2][HID];
    __shared__ float part[416];
    __shared__ float rs[16], rq[16];
    __shared__ float mv[2][2];
    int tid = threadIdx.x;
    int wid = tid >> 5, lane = tid & 31;
    for (int v = tid; v < EMB * HID; v += 512) w1s[v] = w1[v];
    // per-thread matvec role (constant)
    int mr = 0, mcs = 0, mh = 0;
    bool mact = tid < 408;
    if (mact) {
        mr = tid / 204;
        int q = tid - mr * 204;
        mcs = q / 102;
        mh = q - mcs * 102;
    }
    int half = tid >> 8, lt = tid & 255;
    int base = blockIdx.x * 64;
    for (int rr = 0; rr < 64; rr += 2) {
        __syncthreads();
        // load 2 rows
        {
            int grow = base + rr + half;
            int b = grow / NP, j = grow - b * NP;
            const float* src = img + ((size_t)(b * NR) + 1 + j) * EMB;
            ln[half][lt] = src[lt];
            ln[half][lt + 256] = src[lt + 256];
        }
        __syncthreads();
        // fused mean/var: half h handled by warps h*8..h*8+7
        {
            float x0 = ln[half][lt], x1 = ln[half][lt + 256];
            float s = x0 + x1, sq = x0 * x0 + x1 * x1;
            for (int o = 16; o; o >>= 1) {
                s += __shfl_down_sync(0xffffffffu, s, o);
                sq += __shfl_down_sync(0xffffffffu, sq, o);
            }
            if (lane == 0) { rs[wid] = s; rq[wid] = sq; }
            __syncthreads();
            if (tid < 2) {
                float S = 0.f, Q = 0.f;
                for (int w = tid * 8; w < tid * 8 + 8; ++w) { S += rs[w]; Q += rq[w]; }
                float mu = S * (1.0f / EMB);
                mv[tid][0] = mu;
                mv[tid][1] = rsqrtf(Q * (1.0f / EMB) - mu * mu + 1e-5f);
            }
            __syncthreads();
            float mu = mv[half][0], rstd = mv[half][1];
            ln[half][lt] = (ln[half][lt] - mu) * rstd * lng[lt] + lnb[lt];
            ln[half][lt + 256] = (ln[half][lt + 256] - mu) * rstd * lng[lt + 256] + lnb[lt + 256];
        }
        __syncthreads();
        if (mact) {
            float a = 0.f;
            const float* lp = ln[mr] + mcs * 256;
            const float* wp = w1s + mcs * 256 * HID + mh;
            for (int c = 0; c < 256; ++c) a += lp[c] * wp[c * HID];
            part[tid] = a;
        }
        __syncthreads();
        if (tid < 204) {
            int r = tid / 102, h = tid - r * 102;
            gh[r][h] = gelu_f(part[r * 204 + h] + part[r * 204 + 102 + h] + b1[h]);
        }
        __syncthreads();
        if (tid < 2 * KP) {
            int r = tid >= KP ? 1 : 0;
            int p = tid - r * KP;
            float a = b2[p];
            for (int h = 0; h < HID; ++h) a += gh[r][h] * w2[h * KP + p];
            int grw = base + rr + r;
            int bb2 = grw / NP, jj2 = grw - bb2 * NP;
            g_logits[((size_t)bb2 * KP + p) * NP + jj2] = a;
        }
    }
}

// ---------------- K3a: per-word LN+MLP logits (grid 64 x 8) ----------------
__global__ void __launch_bounds__(256) k3a(
    const float* __restrict__ cap, const int* __restrict__ lens,
    const float* __restrict__ lng, const float* __restrict__ lnb,
    const float* __restrict__ w1, const float* __restrict__ b1,
    const float* __restrict__ fw, const float* __restrict__ fb) {
    extern __shared__ float w1s[];
    __shared__ float ln[2][EMB];
    __shared__ float gh[2][HID];
    __shared__ float red[32];
    int i = blockIdx.x, g = blockIdx.y, tid = threadIdx.x;
    int n = lens[i], m = n - 1;
    int kt = m >> 1;
    kt = kt < 4 ? 4 : kt;
    kt = kt > MAXKT ? MAXKT : kt;
    if (kt > 29) kt = 29;
    int row0 = g * 8;
    if (row0 >= m) return;
    for (int v = tid; v < EMB * HID; v += 256) w1s[v] = w1[v];
    const float* capi = cap + (size_t)i * 60 * EMB;
    __syncthreads();
    for (int rw = row0; rw < row0 + 8 && rw < m; rw += 2) {
        for (int r = 0; r < 2; ++r) {
            int wi = rw + r < m ? rw + r : m - 1;
            const float* src = capi + (size_t)(1 + wi) * EMB;
            for (int c = tid; c < EMB; c += 256) ln[r][c] = src[c];
        }
        __syncthreads();
        for (int r = 0; r < 2; ++r) {
            float p = 0.f;
            for (int c = tid; c < EMB; c += 256) p += ln[r][c];
            float mu = bsum(p, red) * (1.0f / EMB);
            p = 0.f;
            for (int c = tid; c < EMB; c += 256) { float d = ln[r][c] - mu; p += d * d; }
            float var = bsum(p, red) * (1.0f / EMB);
            float rstd = rsqrtf(var + 1e-5f);
            for (int c = tid; c < EMB; c += 256)
                ln[r][c] = (ln[r][c] - mu) * rstd * lng[c] + lnb[c];
            __syncthreads();
        }
        if (tid < 2 * HID) {
            int r = tid >= HID ? 1 : 0;
            int h = tid - r * HID;
            float a = 0.f;
            for (int c = 0; c < EMB; ++c) a += ln[r][c] * w1s[c * HID + h];
            gh[r][h] = gelu_f(a + b1[h]);
        }
        __syncthreads();
        if (tid < 64) {
            int r = tid >> 5, t = tid & 31;
            int rowg = rw + r;
            if (t < kt && rowg < m) {
                float a = fb[i * MAXKT + t];
                for (int h = 0; h < HID; ++h)
                    a += gh[r][h] * fw[((size_t)i * HID + h) * MAXKT + t];
                g_lg[(i * 60 + rowg) * 32 + t] = a;
            }
        }
        __syncthreads();
    }
}

// ---------------- K3b: capglo + softmax + aggregation + selcap ----------------
__global__ void __launch_bounds__(256) k3b(
    const float* __restrict__ cap, const int* __restrict__ lens,
    const float* __restrict__ casc) {
    extern __shared__ float rowsb[];   // 30*513
    __shared__ float lgs[60 * 32];
    __shared__ float red[32];
    __shared__ float pb2[256];
    __shared__ float inv2[32];
    __shared__ float cg[EMB];
    int i = blockIdx.x, tid = threadIdx.x;
    int n = lens[i], m = n - 1;
    int kt = m >> 1;
    kt = kt < 4 ? 4 : kt;
    kt = kt > MAXKT ? MAXKT : kt;
    if (kt > 29) kt = 29;
    const float* capi = cap + (size_t)i * 60 * EMB;
    // capglo
    for (int c = tid; c < EMB; c += 256) {
        float s = 0.f;
        for (int r = 0; r < n; ++r) s += capi[(size_t)r * EMB + c];
        cg[c] = s / (float)n;
    }
    // load logits
    for (int v = tid; v < m * 32; v += 256) lgs[v] = g_lg[i * 60 * 32 + v];
    __syncthreads();
    float pv = 0.f;
    for (int c = tid; c < EMB; c += 256) pv += cg[c] * cg[c];
    float nn = bsum(pv, red);
    float rn = 1.f / fmaxf(sqrtf(nn), 1e-12f);
    for (int c = tid; c < EMB; c += 256) g_capglo[i * EMB + c] = cg[c] * rn;
    float cs = casc[0];
    if (tid < kt) {
        float mx = -FLT_MAX;
        for (int r = 0; r < m; ++r) mx = fmaxf(mx, lgs[r * 32 + tid] * cs);
        float z = 0.f;
        for (int r = 0; r < m; ++r) {
            float e = expf(lgs[r * 32 + tid] * cs - mx);
            lgs[r * 32 + tid] = e; z += e;
        }
        float iz = 1.f / z;
        for (int r = 0; r < m; ++r) lgs[r * 32 + tid] *= iz;
    }
    __syncthreads();
    float accA[29], accB[29];
#pragma unroll
    for (int t = 0; t < 29; ++t) { accA[t] = 0.f; accB[t] = 0.f; }
    for (int r = 0; r < m; ++r) {
        float xa = capi[(size_t)(1 + r) * EMB + tid];
        float xb = capi[(size_t)(1 + r) * EMB + tid + 256];
#pragma unroll
        for (int t = 0; t < 29; ++t) {
            if (t < kt) { float w = lgs[r * 32 + t]; accA[t] += w * xa; accB[t] += w * xb; }
        }
    }
    rowsb[tid] = capi[tid];
    rowsb[tid + 256] = capi[tid + 256];
#pragma unroll
    for (int t = 0; t < 29; ++t) {
        if (t < kt) {
            rowsb[(1 + t) * 513 + tid] = accA[t];
            rowsb[(1 + t) * 513 + tid + 256] = accB[t];
        }
    }
    __syncthreads();
    {
        int rrow = tid & 31, q = tid >> 5;
        float s = 0.f;
        if (rrow <= kt) {
            const float* rp = rowsb + rrow * 513 + q * 64;
            for (int k = 0; k < 64; ++k) s += rp[k] * rp[k];
        }
        pb2[q * 32 + rrow] = s;
    }
    __syncthreads();
    if (tid < 32 && tid <= kt) {
        float s = 0.f;
#pragma unroll
        for (int q = 0; q < 8; ++q) s += pb2[q * 32 + tid];
        inv2[tid] = 1.f / fmaxf(sqrtf(s), 1e-12f);
    }
    __syncthreads();
    for (int t = 0; t <= kt; ++t) {
        float iv = inv2[t];
        g_selcap[((size_t)i * 32 + t) * EMB + tid] =
            __uint_as_float(tf32r(rowsb[t * 513 + tid] * iv));
        g_selcap[((size_t)i * 32 + t) * EMB + tid + 256] =
            __uint_as_float(tf32r(rowsb[t * 513 + tid + 256] * iv));
    }
    if (tid == 0) g_nt[i] = kt + 1;
}

// ---------------- K4 ----------------
__global__ void __launch_bounds__(256) k4_score(const float* __restrict__ img) {
    extern __shared__ float sh4[];
    float* cgT = sh4;
    float* xs  = sh4 + 512 * 64;
    int b = blockIdx.x, tid = threadIdx.x;
    for (int v = tid; v < BT * EMB; v += 256) {
        int cp = v >> 9, c = v & 511;
        cgT[c * 64 + cp] = g_capglo[v];
    }
    __syncthreads();
    int capg = tid & 15;
    int rowg = tid >> 4;
    for (int chunk = 0; chunk < 7; ++chunk) {
        int jbase = chunk * 32;
        for (int v = tid; v < 32 * 512; v += 256) {
            int r = v >> 9, c = v & 511;
            int j = jbase + r;
            xs[r * 513 + c] = (j < NP) ? img[((size_t)(b * NR) + 1 + j) * EMB + c] : 0.f;
        }
        __syncthreads();
        ull a00 = 0, a01 = 0, a10 = 0, a11 = 0;
        const float* cgp = cgT + capg * 4;
        const float* x0p = xs + (rowg * 2) * 513;
        const float* x1p = x0p + 513;
        for (int c = 0; c < 512; ++c) {
            ull cgA = *(const ull*)(cgp + c * 64);
            ull cgB = *(const ull*)(cgp + c * 64 + 2);
            float x0 = x0p[c], x1 = x1p[c];
            ull X0 = pk2(x0, x0), X1 = pk2(x1, x1);
            fma2(a00, X0, cgA); fma2(a01, X0, cgB);
            fma2(a10, X1, cgA); fma2(a11, X1, cgB);
        }
#pragma unroll
        for (int r = 0; r < 2; ++r) {
            int j = jbase + rowg * 2 + r;
            if (j < NP) {
                float inv = g_inv[b * NR + 1 + j];
                float slf = g_self[b * NP + j];
                float2 pA = upk2(r ? a10 : a00);
                float2 pB = upk2(r ? a11 : a01);
                int cap0 = capg * 4;
                g_score[((size_t)(cap0 + 0) * BV + b) * NP + j] = slf + pA.x * inv;
                g_score[((size_t)(cap0 + 1) * BV + b) * NP + j] = slf + pA.y * inv;
                g_score[((size_t)(cap0 + 2) * BV + b) * NP + j] = slf + pB.x * inv;
                g_score[((size_t)(cap0 + 3) * BV + b) * NP + j] = slf + pB.y * inv;
            }
        }
        __syncthreads();
    }
}

// ---------------- KW ----------------
__global__ void __launch_bounds__(256) kw_sel(const float* __restrict__ tasc_p) {
    __shared__ float sc[256];
    __shared__ unsigned keyArr[256];
    __shared__ unsigned char kmask[256];
    __shared__ int kidx_sh[128];
    __shared__ int nidx_sh[80];
    __shared__ int cnts[2];
    __shared__ float rowbuf[8][204];
    int tid = threadIdx.x;
    int wq = tid >> 5, ln = tid & 31;
    int i = blockIdx.x, b = blockIdx.y;
    size_t pair = (size_t)i * BV + b;

    float v = (tid < NP) ? g_score[((size_t)i * BV + b) * NP + tid] : 0.f;
    unsigned key = (tid < NP) ? f2k(v) : 0u;
    sc[tid] = v; keyArr[tid] = key;
    unsigned mask = 0, prefix = 0;
    int krem = NKEEP;
    for (int bb = 31; bb >= 0; --bb) {
        unsigned bit = 1u << bb;
        bool pred = ((key & mask) == prefix) && (key & bit);
        int cnt = __syncthreads_count(pred);
        if (cnt >= krem) prefix |= bit; else krem -= cnt;
        mask |= bit;
    }
    bool isKept = false;
    if (tid < NP) {
        if (key > prefix) isKept = true;
        else if (key == prefix) {
            int r = 0;
            for (int j = 0; j < tid; ++j) if (keyArr[j] == prefix) ++r;
            isKept = (r < krem);
        }
    }
    kmask[tid] = isKept ? 1 : 0;
    if (tid == 0) { cnts[0] = 0; cnts[1] = 0; }
    unsigned tu = (prefix & 0x80000000u) ? (prefix & 0x7FFFFFFFu) : ~prefix;
    float thrf = __uint_as_float(tu);
    __syncthreads();
    if (tid < NP) {
        if (isKept) { int p = atomicAdd(&cnts[0], 1); kidx_sh[p] = tid; }
        else        { int p = atomicAdd(&cnts[1], 1); nidx_sh[p] = tid; }
    }
    __syncthreads();
    if (tid >= NKEEP && tid < 128) kidx_sh[tid] = 0;
    if (tid >= 78 && tid < 80) nidx_sh[tid] = 0;
    __syncthreads();
    if (tid < 120) g_kidx[pair * 128 + tid] = kidx_sh[tid];
    if (tid < 80)  g_nidx[pair * 80 + tid] = nidx_sh[tid];

    float tasc = tasc_p[0];
    for (int p = wq; p < 59; p += 8) {
        float val[7]; bool act[7];
        float mx = -FLT_MAX;
        const float* lrow = g_logits + ((size_t)b * KP + (p < KP ? p : 0)) * NP;
#pragma unroll
        for (int q = 0; q < 7; ++q) {
            int j = ln + q * 32;
            bool a = false; float x = -FLT_MAX;
            if (j < NP) {
                bool km = kmask[j] != 0;
                if (p < KP) { if (km) { x = lrow[j] * tasc; a = true; } }
                else        { if (!km) { x = sc[j] - thrf; a = true; } }
            }
            val[q] = x; act[q] = a;
            mx = fmaxf(mx, x);
        }
        for (int o = 16; o; o >>= 1) mx = fmaxf(mx, __shfl_xor_sync(0xffffffffu, mx, o));
        float zz = 0.f;
#pragma unroll
        for (int q = 0; q < 7; ++q) {
            float e = act[q] ? expf(val[q] - mx) : 0.f;
            val[q] = e; zz += e;
        }
        for (int o = 16; o; o >>= 1) zz += __shfl_xor_sync(0xffffffffu, zz, o);
        float iz = 1.f / zz;
#pragma unroll
        for (int q = 0; q < 7; ++q) {
            int j = ln + q * 32;
            if (j < 204)
                rowbuf[wq][j] = act[q] ? __uint_as_float(tf32r(val[q] * iz)) : 0.f;
        }
        __syncwarp();
        if (p < KP) {
            float* wout = g_Wc + pair * 58 * 120 + (size_t)p * 120;
#pragma unroll
            for (int q = 0; q < 4; ++q) {
                int n2 = ln + q * 32;
                if (n2 < 120)
                    wout[n2] = (n2 < NKEEP) ? rowbuf[wq][kidx_sh[n2]] : 0.f;
            }
        } else {
            float* wout = g_wnon + pair * 80;
#pragma unroll
            for (int q = 0; q < 3; ++q) {
                int n2 = ln + q * 32;
                if (n2 < 80)
                    wout[n2] = (n2 < 78) ? rowbuf[wq][nidx_sh[n2]] : 0.f;
            }
        }
        __syncwarp();
    }
}

// ---------------- K5d: gathered compact GEMM, 3-stage pipeline ----------------
__device__ __forceinline__ void k5_stage(float* Xs, const float* imrb, const int* kidx_s,
                                         int z, int kc, int s, int tid) {
    int srow = tid >> 5, scl = (tid & 31) * 8;
    int n = kc * 8 + srow;
    int j = kidx_s[n];
    float* d = Xs + s * (8 * XSS) + srow * XSS + scl;
    const float* g = imrb + (size_t)(1 + j) * EMB + z * 256 + scl;
    cpa16(d, g); cpa16(d + 4, g + 4);
}

__global__ void __launch_bounds__(256, 2) k5d(const float* __restrict__ img) {
    extern __shared__ float dsm[];
    float* Ws = dsm;                   // [64][132] phase A
    float* Xs = dsm + 64 * WCS;        // 3 x [8][264] phase A
    float* R  = dsm;                   // [64][264] phase B overlay
    __shared__ int kidx_s[120];
    __shared__ int nidx_s[80];
    __shared__ float wnon_s[80];
    int tid = threadIdx.x;
    int wq = tid >> 5, ln = tid & 31;
    int i = blockIdx.x, b = blockIdx.y, z = blockIdx.z;
    size_t pair = (size_t)i * BV + b;

    if (tid < 120) kidx_s[tid] = g_kidx[pair * 128 + tid];
    if (tid >= 128 && tid < 208) {
        nidx_s[tid - 128] = g_nidx[pair * 80 + tid - 128];
        wnon_s[tid - 128] = g_wnon[pair * 80 + tid - 128];
    }
    for (int idx = tid; idx < 6 * WCS; idx += 256) Ws[58 * WCS + idx] = 0.f;
    __syncthreads();

    const float* wsrc = g_Wc + pair * 58 * 120;
    for (int idx = tid; idx < 58 * 30; idx += 256) {
        int p = idx / 30, q4 = idx - p * 30;
        cpa16(Ws + p * WCS + q4 * 4, wsrc + p * 120 + q4 * 4);
    }
    asm volatile("cp.async.commit_group;");
    const float* imrb = g_imgr + (size_t)b * NR * EMB;
    k5_stage(Xs, imrb, kidx_s, z, 0, 0, tid);
    asm volatile("cp.async.commit_group;");
    k5_stage(Xs, imrb, kidx_s, z, 1, 1, tid);
    asm volatile("cp.async.commit_group;");

    int mt = wq >> 1, ng = wq & 1;
    float acc[16][4];
#pragma unroll
    for (int t = 0; t < 16; ++t) { acc[t][0] = acc[t][1] = acc[t][2] = acc[t][3] = 0.f; }
    const unsigned* W32 = (const unsigned*)Ws;
    int arow = mt * 16 + (ln >> 2), kk = ln & 3, bc = ng * 128 + (ln >> 2);
    for (int c = 0; c < 15; ++c) {
        asm volatile("cp.async.wait_group 1;");
        __syncthreads();
        if (c + 2 < 15) k5_stage(Xs, imrb, kidx_s, z, c + 2, (c + 2) % 3, tid);
        asm volatile("cp.async.commit_group;");
        const unsigned* XB = (const unsigned*)(Xs + (c % 3) * (8 * XSS));
        unsigned a0 = W32[arow * WCS + c * 8 + kk];
        unsigned a1 = W32[(arow + 8) * WCS + c * 8 + kk];
        unsigned a2 = W32[arow * WCS + c * 8 + kk + 4];
        unsigned a3 = W32[(arow + 8) * WCS + c * 8 + kk + 4];
#pragma unroll
        for (int nt = 0; nt < 16; ++nt) {
            unsigned b0 = XB[kk * XSS + bc + nt * 8];
            unsigned b1 = XB[(kk + 4) * XSS + bc + nt * 8];
            mma8(acc[nt], a0, a1, a2, a3, b0, b1);
        }
    }
    __syncthreads();

    int r0 = mt * 16 + (ln >> 2);
#pragma unroll
    for (int nt = 0; nt < 16; ++nt) {
        int col = ng * 128 + nt * 8 + 2 * (ln & 3);
        *(float2*)(R + r0 * XSS + col) = make_float2(
            __uint_as_float(tf32r(acc[nt][0])), __uint_as_float(tf32r(acc[nt][1])));
        *(float2*)(R + (r0 + 8) * XSS + col) = make_float2(
            __uint_as_float(tf32r(acc[nt][2])), __uint_as_float(tf32r(acc[nt][3])));
    }
    __syncthreads();

    {
        float acce = 0.f;
        const float* base = imrb + EMB + z * 256 + tid;
#pragma unroll 4
        for (int q = 0; q < 80; ++q)
            acce += wnon_s[q] * base[(size_t)nidx_s[q] * EMB];
        R[58 * XSS + tid] = __uint_as_float(tf32r(acce));
    }
    __syncthreads();

    for (int r = wq; r < 59; r += 8) {
        float s = 0.f;
        for (int c = ln; c < 256; c += 32) { float x = R[r * XSS + c]; s += x * x; }
        for (int o = 16; o; o >>= 1) s += __shfl_down_sync(0xffffffffu, s, o);
        if (ln == 0) g_N2[(pair * 2 + z) * 64 + r] = s;
    }
    const float* clsr = img + (size_t)b * NR * EMB + z * 256;
    float* So = g_S + ((pair * 2 + z) * 32) * 64;
    for (int t = wq; t < 32; t += 8) {
        const float* sp = g_selcap + ((size_t)i * 32 + t) * EMB + z * 256;
        float s = 0.f;
        for (int c = ln; c < 256; c += 32) s += sp[c] * clsr[c];
        for (int o = 16; o; o >>= 1) s += __shfl_down_sync(0xffffffffu, s, o);
        if (ln == 0) So[t * 64 + 59] = s;
    }
    {
        int mt2 = wq >> 2, ng2 = wq & 3;
        float sacc[2][4];
#pragma unroll
        for (int t = 0; t < 2; ++t) { sacc[t][0] = sacc[t][1] = sacc[t][2] = sacc[t][3] = 0.f; }
        int mrow = mt2 * 16 + (ln >> 2);
        const float* scap = g_selcap + (size_t)i * 32 * EMB + z * 256;
        for (int kc = 0; kc < 32; ++kc) {
            int k0 = kc * 8 + (ln & 3);
            unsigned a0 = __float_as_uint(scap[(size_t)mrow * EMB + k0]);
            unsigned a1 = __float_as_uint(scap[(size_t)(mrow + 8) * EMB + k0]);
            unsigned a2 = __float_as_uint(scap[(size_t)mrow * EMB + k0 + 4]);
            unsigned a3 = __float_as_uint(scap[(size_t)(mrow + 8) * EMB + k0 + 4]);
#pragma unroll
            for (int nt = 0; nt < 2; ++nt) {
                int tok = ng2 * 16 + nt * 8 + (ln >> 2);
                unsigned b0 = __float_as_uint(R[tok * XSS + k0]);
                unsigned b1 = __float_as_uint(R[tok * XSS + k0 + 4]);
                mma8(sacc[nt], a0, a1, a2, a3, b0, b1);
            }
        }
        int t0 = mt2 * 16 + (ln >> 2);
#pragma unroll
        for (int nt = 0; nt < 2; ++nt) {
            int col = ng2 * 16 + nt * 8 + 2 * (ln & 3);
            if (col < 59)     So[t0 * 64 + col] = sacc[nt][0];
            if (col + 1 < 59) So[t0 * 64 + col + 1] = sacc[nt][1];
            if (col < 59)     So[(t0 + 8) * 64 + col] = sacc[nt][2];
            if (col + 1 < 59) So[(t0 + 8) * 64 + col + 1] = sacc[nt][3];
        }
    }
}

// ---------------- K6 ----------------
__global__ void __launch_bounds__(64) k6_fin(float* __restrict__ out) {
    __shared__ float rinv[64];
    __shared__ float wacc[2];
    int i = blockIdx.x, b = blockIdx.y, tid = threadIdx.x;
    int wq = tid >> 5, ln = tid & 31;
    size_t pair = (size_t)i * BV + b;
    const float* Sa = g_S + pair * 2 * 2048;
    const float* Sb = Sa + 2048;
    const float* Na = g_N2 + pair * 128;
    if (tid < 59) {
        float n2 = Na[tid] + Na[64 + tid];
        rinv[tid] = 1.f / fmaxf(sqrtf(fmaxf(n2, 0.f)), 1e-12f);
    }
    if (tid < 2) wacc[tid] = 0.f;
    __syncthreads();
    int T = g_nt[i];
    float cinv = g_inv[b * NR];
    float acc = 0.f;
    for (int t = wq; t < T; t += 2) {
        float val;
        {
            int col = (ln == 0) ? 59 : ln - 1;
            float s = Sa[t * 64 + col] + Sb[t * 64 + col];
            val = (ln == 0) ? s * cinv : s * rinv[ln - 1];
        }
        if (ln < 28) {
            int col = ln + 31;
            float s = Sa[t * 64 + col] + Sb[t * 64 + col];
            val = fmaxf(val, s * rinv[col]);
        }
        for (int o = 16; o; o >>= 1) val = fmaxf(val, __shfl_xor_sync(0xffffffffu, val, o));
        if (ln == 0) acc += val;
    }
    if (ln == 0) wacc[wq] = acc;
    __syncthreads();
    if (tid == 0) out[b * BT + i] = (wacc[0] + wacc[1]) / (float)T;
}

extern "C" void kernel_launch(void* const* d_in, const int* in_sizes, int n_in,
                              void* d_out, int out_size) {
    const float* img   = (const float*)d_in[0];
    const float* cap   = (const float*)d_in[1];
    const int*   lens  = (const int*)d_in[2];
    const float* talng = (const float*)d_in[3];
    const float* talnb = (const float*)d_in[4];
    const float* taw1  = (const float*)d_in[5];
    const float* tab1  = (const float*)d_in[6];
    const float* taw2  = (const float*)d_in[7];
    const float* tab2  = (const float*)d_in[8];
    const float* tasc  = (const float*)d_in[9];
    const float* calng = (const float*)d_in[10];
    const float* calnb = (const float*)d_in[11];
    const float* caw1  = (const float*)d_in[12];
    const float* cab1  = (const float*)d_in[13];
    const float* casc  = (const float*)d_in[14];
    const float* fw    = (const float*)d_in[15];
    const float* fb    = (const float*)d_in[16];
    float* out = (float*)d_out;

    cudaFuncSetAttribute(k2_logits, cudaFuncAttributeMaxDynamicSharedMemorySize, 208896);
    cudaFuncSetAttribute(k3a,       cudaFuncAttributeMaxDynamicSharedMemorySize, 208896);
    cudaFuncSetAttribute(k3b,       cudaFuncAttributeMaxDynamicSharedMemorySize, 61696);
    cudaFuncSetAttribute(k4_score,  cudaFuncAttributeMaxDynamicSharedMemorySize, 196736);
    cudaFuncSetAttribute(k5d,       cudaFuncAttributeMaxDynamicSharedMemorySize, 67584);

    k0r<<<1024, 256>>>(img);
    k1_img<<<BV, 256>>>(img);
    k2_logits<<<392, 512, 208896>>>(img, talng, talnb, taw1, tab1, taw2, tab2);
    k3a<<<dim3(BT, 8), 256, 208896>>>(cap, lens, calng, calnb, caw1, cab1, fw, fb);
    k3b<<<BT, 256, 61696>>>(cap, lens, casc);
    k4_score<<<BV, 256, 196736>>>(img);
    kw_sel<<<dim3(BT, BV), 256>>>(tasc);
    k5d<<<dim3(BT, BV, 2), 256, 67584>>>(img);
    k6_fin<<<dim3(BT, BV), 64>>>(out);
}

// round 15
// speedup vs baseline: 1.0658x; 1.0658x over previous
#include <cuda_runtime.h>
#include <cuda_bf16.h>
#include <float.h>
#include <math.h>

#define BV 128
#define BT 64
#define EMB 512
#define NP 196
#define NR 197
#define NKEEP 118
#define KP 58
#define HID 102
#define MAXKT 100
#define WCS 132
#define XSS 264

typedef unsigned long long ull;

__device__ float g_inv[BV * NR];
__device__ float g_self[BV * NP];
__device__ float g_logits[BV * KP * NP];               // transposed [b][p][j]
__device__ float g_capglo[BT * EMB];
__device__ float g_selcap[BT * 32 * EMB];
__device__ int   g_nt[BT];
__device__ float g_score[BT * BV * NP];
__device__ float g_imgr[(size_t)BV * NR * EMB];        // tf32-rounded rows
__device__ float g_Wc[(size_t)BT * BV * 58 * 120];     // compact kept weights (tf32)
__device__ int   g_kidx[BT * BV * 128];
__device__ int   g_nidx[BT * BV * 80];
__device__ float g_wnon[BT * BV * 80];
__device__ float g_S[(size_t)BT * BV * 2 * 32 * 64];
__device__ float g_N2[BT * BV * 2 * 64];
__device__ float g_lg[BT * 60 * 32];                   // caption word logits

__device__ __forceinline__ float gelu_f(float x) {
    return 0.5f * x * (1.0f + erff(x * 0.70710678118654752440f));
}
__device__ __forceinline__ ull pk2(float lo, float hi) {
    ull r; asm("mov.b64 %0,{%1,%2};" : "=l"(r) : "f"(lo), "f"(hi)); return r;
}
__device__ __forceinline__ void fma2(ull& a, ull x, ull w) {
    asm("fma.rn.f32x2 %0,%1,%2,%0;" : "+l"(a) : "l"(x), "l"(w));
}
__device__ __forceinline__ float2 upk2(ull a) {
    float lo, hi; asm("mov.b64 {%0,%1},%2;" : "=f"(lo), "=f"(hi) : "l"(a));
    return make_float2(lo, hi);
}
__device__ __forceinline__ unsigned f2k(float f) {
    unsigned u = __float_as_uint(f);
    return (u & 0x80000000u) ? ~u : (u | 0x80000000u);
}
__device__ __forceinline__ unsigned tf32r(float x) {
    unsigned r; asm("cvt.rna.tf32.f32 %0,%1;" : "=r"(r) : "f"(x)); return r;
}
__device__ __forceinline__ void mma8(float* d, unsigned a0, unsigned a1, unsigned a2,
                                     unsigned a3, unsigned b0, unsigned b1) {
    asm("mma.sync.aligned.m16n8k8.row.col.f32.tf32.tf32.f32 "
        "{%0,%1,%2,%3},{%4,%5,%6,%7},{%8,%9},{%0,%1,%2,%3};"
        : "+f"(d[0]), "+f"(d[1]), "+f"(d[2]), "+f"(d[3])
        : "r"(a0), "r"(a1), "r"(a2), "r"(a3), "r"(b0), "r"(b1));
}
__device__ __forceinline__ void cpa16(void* s, const void* g) {
    unsigned sa = (unsigned)__cvta_generic_to_shared(s);
    asm volatile("cp.async.cg.shared.global [%0], [%1], 16;" :: "r"(sa), "l"(g));
}

__device__ __forceinline__ float bsum(float v, float* buf) {
    for (int o = 16; o; o >>= 1) v += __shfl_down_sync(0xffffffffu, v, o);
    int w = threadIdx.x >> 5, l = threadIdx.x & 31;
    if (l == 0) buf[w] = v;
    __syncthreads();
    float r = (threadIdx.x < 8) ? buf[threadIdx.x] : 0.0f;
    if (w == 0) {
        for (int o = 4; o; o >>= 1) r += __shfl_down_sync(0xffffffffu, r, o);
        if (l == 0) buf[0] = r;
    }
    __syncthreads();
    float res = buf[0];
    __syncthreads();
    return res;
}

// ---------------- K0r ----------------
__global__ void __launch_bounds__(256) k0r(const float* __restrict__ img) {
    size_t total = (size_t)BV * NR * 128;
    for (size_t idx = (size_t)blockIdx.x * 256 + threadIdx.x; idx < total;
         idx += (size_t)gridDim.x * 256) {
        float4 v = *(const float4*)(img + idx * 4);
        v.x = __uint_as_float(tf32r(v.x));
        v.y = __uint_as_float(tf32r(v.y));
        v.z = __uint_as_float(tf32r(v.z));
        v.w = __uint_as_float(tf32r(v.w));
        *(float4*)(g_imgr + idx * 4) = v;
    }
}

// ---------------- K1 ----------------
__global__ void __launch_bounds__(256) k1_img(const float* __restrict__ img) {
    int b = blockIdx.x;
    const float* base = img + (size_t)b * NR * EMB;
    __shared__ float sm[EMB];
    __shared__ float red[32];
    int tid = threadIdx.x;
    for (int c = tid; c < EMB; c += 256) {
        float s = 0.f;
        for (int j = 1; j < NR; ++j) s += base[(size_t)j * EMB + c];
        sm[c] = s * (1.0f / NP);
    }
    __syncthreads();
    float pv = 0.f;
    for (int c = tid; c < EMB; c += 256) { float v = sm[c]; pv += v * v; }
    float nn = bsum(pv, red);
    float rn = 1.f / fmaxf(sqrtf(nn), 1e-12f);
    for (int c = tid; c < EMB; c += 256) sm[c] *= rn;
    __syncthreads();
    int wid = tid >> 5, lane = tid & 31;
    for (int j = wid; j < NR; j += 8) {
        const float* r = base + (size_t)j * EMB;
        float s2 = 0.f, sd = 0.f;
        for (int k = lane; k < EMB; k += 32) { float v = r[k]; s2 += v * v; sd += v * sm[k]; }
        for (int o = 16; o; o >>= 1) {
            s2 += __shfl_down_sync(0xffffffffu, s2, o);
            sd += __shfl_down_sync(0xffffffffu, sd, o);
        }
        if (lane == 0) {
            float inv = 1.f / fmaxf(sqrtf(s2), 1e-12f);
            g_inv[b * NR + j] = inv;
            if (j >= 1) g_self[b * NP + j - 1] = sd * inv;
        }
    }
}

// ---------------- K2 (R12 version, transposed logit store) ----------------
__global__ void __launch_bounds__(256) k2_logits(
    const float* __restrict__ img,
    const float* __restrict__ lng, const float* __restrict__ lnb,
    const float* __restrict__ w1, const float* __restrict__ b1,
    const float* __restrict__ w2, const float* __restrict__ b2) {
    extern __shared__ float w1s[];
    __shared__ float ln[2][EMB];
    __shared__ float gh[2][HID];
    __shared__ float red[32];
    int tid = threadIdx.x;
    for (int v = tid; v < EMB * HID; v += 256) w1s[v] = w1[v];
    int base = blockIdx.x * 64;
    for (int rr = 0; rr < 64; rr += 2) {
        __syncthreads();
        for (int r = 0; r < 2; ++r) {
            int grow = base + rr + r;
            int b = grow / NP, j = grow - b * NP;
            const float* src = img + ((size_t)(b * NR) + 1 + j) * EMB;
            for (int c = tid; c < EMB; c += 256) ln[r][c] = src[c];
        }
        __syncthreads();
        for (int r = 0; r < 2; ++r) {
            float p = 0.f;
            for (int c = tid; c < EMB; c += 256) p += ln[r][c];
            float mu = bsum(p, red) * (1.0f / EMB);
            p = 0.f;
            for (int c = tid; c < EMB; c += 256) { float d = ln[r][c] - mu; p += d * d; }
            float var = bsum(p, red) * (1.0f / EMB);
            float rstd = rsqrtf(var + 1e-5f);
            for (int c = tid; c < EMB; c += 256)
                ln[r][c] = (ln[r][c] - mu) * rstd * lng[c] + lnb[c];
            __syncthreads();
        }
        if (tid < 2 * HID) {
            int r = tid >= HID ? 1 : 0;
            int h = tid - r * HID;
            float a = 0.f;
            for (int c = 0; c < EMB; ++c) a += ln[r][c] * w1s[c * HID + h];
            gh[r][h] = gelu_f(a + b1[h]);
        }
        __syncthreads();
        if (tid < 2 * KP) {
            int r = tid >= KP ? 1 : 0;
            int p = tid - r * KP;
            float a = b2[p];
            for (int h = 0; h < HID; ++h) a += gh[r][h] * w2[h * KP + p];
            int grw = base + rr + r;
            int bb2 = grw / NP, jj2 = grw - bb2 * NP;
            g_logits[((size_t)bb2 * KP + p) * NP + jj2] = a;
        }
    }
}

// ---------------- K3a: per-word LN+MLP logits (grid 64 x 8) ----------------
__global__ void __launch_bounds__(256) k3a(
    const float* __restrict__ cap, const int* __restrict__ lens,
    const float* __restrict__ lng, const float* __restrict__ lnb,
    const float* __restrict__ w1, const float* __restrict__ b1,
    const float* __restrict__ fw, const float* __restrict__ fb) {
    extern __shared__ float w1s[];
    __shared__ float ln[2][EMB];
    __shared__ float gh[2][HID];
    __shared__ float red[32];
    int i = blockIdx.x, g = blockIdx.y, tid = threadIdx.x;
    int n = lens[i], m = n - 1;
    int kt = m >> 1;
    kt = kt < 4 ? 4 : kt;
    kt = kt > MAXKT ? MAXKT : kt;
    if (kt > 29) kt = 29;
    int row0 = g * 8;
    if (row0 >= m) return;
    for (int v = tid; v < EMB * HID; v += 256) w1s[v] = w1[v];
    const float* capi = cap + (size_t)i * 60 * EMB;
    __syncthreads();
    for (int rw = row0; rw < row0 + 8 && rw < m; rw += 2) {
        for (int r = 0; r < 2; ++r) {
            int wi = rw + r < m ? rw + r : m - 1;
            const float* src = capi + (size_t)(1 + wi) * EMB;
            for (int c = tid; c < EMB; c += 256) ln[r][c] = src[c];
        }
        __syncthreads();
        for (int r = 0; r < 2; ++r) {
            float p = 0.f;
            for (int c = tid; c < EMB; c += 256) p += ln[r][c];
            float mu = bsum(p, red) * (1.0f / EMB);
            p = 0.f;
            for (int c = tid; c < EMB; c += 256) { float d = ln[r][c] - mu; p += d * d; }
            float var = bsum(p, red) * (1.0f / EMB);
            float rstd = rsqrtf(var + 1e-5f);
            for (int c = tid; c < EMB; c += 256)
                ln[r][c] = (ln[r][c] - mu) * rstd * lng[c] + lnb[c];
            __syncthreads();
        }
        if (tid < 2 * HID) {
            int r = tid >= HID ? 1 : 0;
            int h = tid - r * HID;
            float a = 0.f;
            for (int c = 0; c < EMB; ++c) a += ln[r][c] * w1s[c * HID + h];
            gh[r][h] = gelu_f(a + b1[h]);
        }
        __syncthreads();
        if (tid < 64) {
            int r = tid >> 5, t = tid & 31;
            int rowg = rw + r;
            if (t < kt && rowg < m) {
                float a = fb[i * MAXKT + t];
                for (int h = 0; h < HID; ++h)
                    a += gh[r][h] * fw[((size_t)i * HID + h) * MAXKT + t];
                g_lg[(i * 60 + rowg) * 32 + t] = a;
            }
        }
        __syncthreads();
    }
}

// ---------------- K3b: capglo + softmax + aggregation + selcap ----------------
__global__ void __launch_bounds__(256) k3b(
    const float* __restrict__ cap, const int* __restrict__ lens,
    const float* __restrict__ casc) {
    extern __shared__ float rowsb[];   // 30*513
    __shared__ float lgs[60 * 32];
    __shared__ float red[32];
    __shared__ float pb2[256];
    __shared__ float inv2[32];
    __shared__ float cg[EMB];
    int i = blockIdx.x, tid = threadIdx.x;
    int n = lens[i], m = n - 1;
    int kt = m >> 1;
    kt = kt < 4 ? 4 : kt;
    kt = kt > MAXKT ? MAXKT : kt;
    if (kt > 29) kt = 29;
    const float* capi = cap + (size_t)i * 60 * EMB;
    for (int c = tid; c < EMB; c += 256) {
        float s = 0.f;
        for (int r = 0; r < n; ++r) s += capi[(size_t)r * EMB + c];
        cg[c] = s / (float)n;
    }
    for (int v = tid; v < m * 32; v += 256) lgs[v] = g_lg[i * 60 * 32 + v];
    __syncthreads();
    float pv = 0.f;
    for (int c = tid; c < EMB; c += 256) pv += cg[c] * cg[c];
    float nn = bsum(pv, red);
    float rn = 1.f / fmaxf(sqrtf(nn), 1e-12f);
    for (int c = tid; c < EMB; c += 256) g_capglo[i * EMB + c] = cg[c] * rn;
    float cs = casc[0];
    if (tid < kt) {
        float mx = -FLT_MAX;
        for (int r = 0; r < m; ++r) mx = fmaxf(mx, lgs[r * 32 + tid] * cs);
        float z = 0.f;
        for (int r = 0; r < m; ++r) {
            float e = expf(lgs[r * 32 + tid] * cs - mx);
            lgs[r * 32 + tid] = e; z += e;
        }
        float iz = 1.f / z;
        for (int r = 0; r < m; ++r) lgs[r * 32 + tid] *= iz;
    }
    __syncthreads();
    float accA[29], accB[29];
#pragma unroll
    for (int t = 0; t < 29; ++t) { accA[t] = 0.f; accB[t] = 0.f; }
    for (int r = 0; r < m; ++r) {
        float xa = capi[(size_t)(1 + r) * EMB + tid];
        float xb = capi[(size_t)(1 + r) * EMB + tid + 256];
#pragma unroll
        for (int t = 0; t < 29; ++t) {
            if (t < kt) { float w = lgs[r * 32 + t]; accA[t] += w * xa; accB[t] += w * xb; }
        }
    }
    rowsb[tid] = capi[tid];
    rowsb[tid + 256] = capi[tid + 256];
#pragma unroll
    for (int t = 0; t < 29; ++t) {
        if (t < kt) {
            rowsb[(1 + t) * 513 + tid] = accA[t];
            rowsb[(1 + t) * 513 + tid + 256] = accB[t];
        }
    }
    __syncthreads();
    {
        int rrow = tid & 31, q = tid >> 5;
        float s = 0.f;
        if (rrow <= kt) {
            const float* rp = rowsb + rrow * 513 + q * 64;
            for (int k = 0; k < 64; ++k) s += rp[k] * rp[k];
        }
        pb2[q * 32 + rrow] = s;
    }
    __syncthreads();
    if (tid < 32 && tid <= kt) {
        float s = 0.f;
#pragma unroll
        for (int q = 0; q < 8; ++q) s += pb2[q * 32 + tid];
        inv2[tid] = 1.f / fmaxf(sqrtf(s), 1e-12f);
    }
    __syncthreads();
    for (int t = 0; t <= kt; ++t) {
        float iv = inv2[t];
        g_selcap[((size_t)i * 32 + t) * EMB + tid] =
            __uint_as_float(tf32r(rowsb[t * 513 + tid] * iv));
        g_selcap[((size_t)i * 32 + t) * EMB + tid + 256] =
            __uint_as_float(tf32r(rowsb[t * 513 + tid + 256] * iv));
    }
    if (tid == 0) g_nt[i] = kt + 1;
}

// ---------------- K4 ----------------
__global__ void __launch_bounds__(256) k4_score(const float* __restrict__ img) {
    extern __shared__ float sh4[];
    float* cgT = sh4;
    float* xs  = sh4 + 512 * 64;
    int b = blockIdx.x, tid = threadIdx.x;
    for (int v = tid; v < BT * EMB; v += 256) {
        int cp = v >> 9, c = v & 511;
        cgT[c * 64 + cp] = g_capglo[v];
    }
    __syncthreads();
    int capg = tid & 15;
    int rowg = tid >> 4;
    for (int chunk = 0; chunk < 7; ++chunk) {
        int jbase = chunk * 32;
        for (int v = tid; v < 32 * 512; v += 256) {
            int r = v >> 9, c = v & 511;
            int j = jbase + r;
            xs[r * 513 + c] = (j < NP) ? img[((size_t)(b * NR) + 1 + j) * EMB + c] : 0.f;
        }
        __syncthreads();
        ull a00 = 0, a01 = 0, a10 = 0, a11 = 0;
        const float* cgp = cgT + capg * 4;
        const float* x0p = xs + (rowg * 2) * 513;
        const float* x1p = x0p + 513;
        for (int c = 0; c < 512; ++c) {
            ull cgA = *(const ull*)(cgp + c * 64);
            ull cgB = *(const ull*)(cgp + c * 64 + 2);
            float x0 = x0p[c], x1 = x1p[c];
            ull X0 = pk2(x0, x0), X1 = pk2(x1, x1);
            fma2(a00, X0, cgA); fma2(a01, X0, cgB);
            fma2(a10, X1, cgA); fma2(a11, X1, cgB);
        }
#pragma unroll
        for (int r = 0; r < 2; ++r) {
            int j = jbase + rowg * 2 + r;
            if (j < NP) {
                float inv = g_inv[b * NR + 1 + j];
                float slf = g_self[b * NP + j];
                float2 pA = upk2(r ? a10 : a00);
                float2 pB = upk2(r ? a11 : a01);
                int cap0 = capg * 4;
                g_score[((size_t)(cap0 + 0) * BV + b) * NP + j] = slf + pA.x * inv;
                g_score[((size_t)(cap0 + 1) * BV + b) * NP + j] = slf + pA.y * inv;
                g_score[((size_t)(cap0 + 2) * BV + b) * NP + j] = slf + pB.x * inv;
                g_score[((size_t)(cap0 + 3) * BV + b) * NP + j] = slf + pB.y * inv;
            }
        }
        __syncthreads();
    }
}

// ---------------- KW ----------------
__global__ void __launch_bounds__(256) kw_sel(const float* __restrict__ tasc_p) {
    __shared__ float sc[256];
    __shared__ unsigned keyArr[256];
    __shared__ unsigned char kmask[256];
    __shared__ int kidx_sh[128];
    __shared__ int nidx_sh[80];
    __shared__ int cnts[2];
    __shared__ float rowbuf[8][204];
    int tid = threadIdx.x;
    int wq = tid >> 5, ln = tid & 31;
    int i = blockIdx.x, b = blockIdx.y;
    size_t pair = (size_t)i * BV + b;

    float v = (tid < NP) ? g_score[((size_t)i * BV + b) * NP + tid] : 0.f;
    unsigned key = (tid < NP) ? f2k(v) : 0u;
    sc[tid] = v; keyArr[tid] = key;
    unsigned mask = 0, prefix = 0;
    int krem = NKEEP;
    for (int bb = 31; bb >= 0; --bb) {
        unsigned bit = 1u << bb;
        bool pred = ((key & mask) == prefix) && (key & bit);
        int cnt = __syncthreads_count(pred);
        if (cnt >= krem) prefix |= bit; else krem -= cnt;
        mask |= bit;
    }
    bool isKept = false;
    if (tid < NP) {
        if (key > prefix) isKept = true;
        else if (key == prefix) {
            int r = 0;
            for (int j = 0; j < tid; ++j) if (keyArr[j] == prefix) ++r;
            isKept = (r < krem);
        }
    }
    kmask[tid] = isKept ? 1 : 0;
    if (tid == 0) { cnts[0] = 0; cnts[1] = 0; }
    unsigned tu = (prefix & 0x80000000u) ? (prefix & 0x7FFFFFFFu) : ~prefix;
    float thrf = __uint_as_float(tu);
    __syncthreads();
    if (tid < NP) {
        if (isKept) { int p = atomicAdd(&cnts[0], 1); kidx_sh[p] = tid; }
        else        { int p = atomicAdd(&cnts[1], 1); nidx_sh[p] = tid; }
    }
    __syncthreads();
    if (tid >= NKEEP && tid < 128) kidx_sh[tid] = 0;
    if (tid >= 78 && tid < 80) nidx_sh[tid] = 0;
    __syncthreads();
    if (tid < 120) g_kidx[pair * 128 + tid] = kidx_sh[tid];
    if (tid < 80)  g_nidx[pair * 80 + tid] = nidx_sh[tid];

    float tasc = tasc_p[0];
    for (int p = wq; p < 59; p += 8) {
        float val[7]; bool act[7];
        float mx = -FLT_MAX;
        const float* lrow = g_logits + ((size_t)b * KP + (p < KP ? p : 0)) * NP;
#pragma unroll
        for (int q = 0; q < 7; ++q) {
            int j = ln + q * 32;
            bool a = false; float x = -FLT_MAX;
            if (j < NP) {
                bool km = kmask[j] != 0;
                if (p < KP) { if (km) { x = lrow[j] * tasc; a = true; } }
                else        { if (!km) { x = sc[j] - thrf; a = true; } }
            }
            val[q] = x; act[q] = a;
            mx = fmaxf(mx, x);
        }
        for (int o = 16; o; o >>= 1) mx = fmaxf(mx, __shfl_xor_sync(0xffffffffu, mx, o));
        float zz = 0.f;
#pragma unroll
        for (int q = 0; q < 7; ++q) {
            float e = act[q] ? expf(val[q] - mx) : 0.f;
            val[q] = e; zz += e;
        }
        for (int o = 16; o; o >>= 1) zz += __shfl_xor_sync(0xffffffffu, zz, o);
        float iz = 1.f / zz;
#pragma unroll
        for (int q = 0; q < 7; ++q) {
            int j = ln + q * 32;
            if (j < 204)
                rowbuf[wq][j] = act[q] ? __uint_as_float(tf32r(val[q] * iz)) : 0.f;
        }
        __syncwarp();
        if (p < KP) {
            float* wout = g_Wc + pair * 58 * 120 + (size_t)p * 120;
#pragma unroll
            for (int q = 0; q < 4; ++q) {
                int n2 = ln + q * 32;
                if (n2 < 120)
                    wout[n2] = (n2 < NKEEP) ? rowbuf[wq][kidx_sh[n2]] : 0.f;
            }
        } else {
            float* wout = g_wnon + pair * 80;
#pragma unroll
            for (int q = 0; q < 3; ++q) {
                int n2 = ln + q * 32;
                if (n2 < 80)
                    wout[n2] = (n2 < 78) ? rowbuf[wq][nidx_sh[n2]] : 0.f;
            }
        }
        __syncwarp();
    }
}

// ---------------- K5d: gathered compact GEMM, 2-stage (R12) ----------------
__device__ __forceinline__ void k5_stage(float* Xs, const float* imrb, const int* kidx_s,
                                         int z, int kc, int s, int tid) {
    int srow = tid >> 5, scl = (tid & 31) * 8;
    int n = kc * 8 + srow;
    int j = kidx_s[n];
    float* d = Xs + s * (8 * XSS) + srow * XSS + scl;
    const float* g = imrb + (size_t)(1 + j) * EMB + z * 256 + scl;
    cpa16(d, g); cpa16(d + 4, g + 4);
}

__global__ void __launch_bounds__(256, 2) k5d(const float* __restrict__ img) {
    extern __shared__ float dsm[];
    float* Ws = dsm;                   // [64][132] phase A
    float* Xs = dsm + 64 * WCS;        // 2 x [8][264] phase A
    float* R  = dsm;                   // [64][264] phase B overlay
    __shared__ int kidx_s[120];
    __shared__ int nidx_s[80];
    __shared__ float wnon_s[80];
    int tid = threadIdx.x;
    int wq = tid >> 5, ln = tid & 31;
    int i = blockIdx.x, b = blockIdx.y, z = blockIdx.z;
    size_t pair = (size_t)i * BV + b;

    if (tid < 120) kidx_s[tid] = g_kidx[pair * 128 + tid];
    if (tid >= 128 && tid < 208) {
        nidx_s[tid - 128] = g_nidx[pair * 80 + tid - 128];
        wnon_s[tid - 128] = g_wnon[pair * 80 + tid - 128];
    }
    for (int idx = tid; idx < 6 * WCS; idx += 256) Ws[58 * WCS + idx] = 0.f;
    __syncthreads();

    const float* wsrc = g_Wc + pair * 58 * 120;
    for (int idx = tid; idx < 58 * 30; idx += 256) {
        int p = idx / 30, q4 = idx - p * 30;
        cpa16(Ws + p * WCS + q4 * 4, wsrc + p * 120 + q4 * 4);
    }
    asm volatile("cp.async.commit_group;");
    const float* imrb = g_imgr + (size_t)b * NR * EMB;
    k5_stage(Xs, imrb, kidx_s, z, 0, 0, tid);
    asm volatile("cp.async.commit_group;");
    k5_stage(Xs, imrb, kidx_s, z, 1, 1, tid);
    asm volatile("cp.async.commit_group;");

    int mt = wq >> 1, ng = wq & 1;
    float acc[16][4];
#pragma unroll
    for (int t = 0; t < 16; ++t) { acc[t][0] = acc[t][1] = acc[t][2] = acc[t][3] = 0.f; }
    const unsigned* W32 = (const unsigned*)Ws;
    int arow = mt * 16 + (ln >> 2), kk = ln & 3, bc = ng * 128 + (ln >> 2);
    for (int c = 0; c < 15; ++c) {
        asm volatile("cp.async.wait_group 1;");
        __syncthreads();
        const unsigned* XB = (const unsigned*)(Xs + (c & 1) * (8 * XSS));
        unsigned a0 = W32[arow * WCS + c * 8 + kk];
        unsigned a1 = W32[(arow + 8) * WCS + c * 8 + kk];
        unsigned a2 = W32[arow * WCS + c * 8 + kk + 4];
        unsigned a3 = W32[(arow + 8) * WCS + c * 8 + kk + 4];
#pragma unroll
        for (int nt = 0; nt < 16; ++nt) {
            unsigned b0 = XB[kk * XSS + bc + nt * 8];
            unsigned b1 = XB[(kk + 4) * XSS + bc + nt * 8];
            mma8(acc[nt], a0, a1, a2, a3, b0, b1);
        }
        __syncthreads();
        if (c + 2 < 15) k5_stage(Xs, imrb, kidx_s, z, c + 2, c & 1, tid);
        asm volatile("cp.async.commit_group;");
    }

    int r0 = mt * 16 + (ln >> 2);
#pragma unroll
    for (int nt = 0; nt < 16; ++nt) {
        int col = ng * 128 + nt * 8 + 2 * (ln & 3);
        *(float2*)(R + r0 * XSS + col) = make_float2(
            __uint_as_float(tf32r(acc[nt][0])), __uint_as_float(tf32r(acc[nt][1])));
        *(float2*)(R + (r0 + 8) * XSS + col) = make_float2(
            __uint_as_float(tf32r(acc[nt][2])), __uint_as_float(tf32r(acc[nt][3])));
    }
    __syncthreads();

    {
        float acce = 0.f;
        const float* base = imrb + EMB + z * 256 + tid;
#pragma unroll 4
        for (int q = 0; q < 80; ++q)
            acce += wnon_s[q] * base[(size_t)nidx_s[q] * EMB];
        R[58 * XSS + tid] = __uint_as_float(tf32r(acce));
    }
    __syncthreads();

    for (int r = wq; r < 59; r += 8) {
        float s = 0.f;
        for (int c = ln; c < 256; c += 32) { float x = R[r * XSS + c]; s += x * x; }
        for (int o = 16; o; o >>= 1) s += __shfl_down_sync(0xffffffffu, s, o);
        if (ln == 0) g_N2[(pair * 2 + z) * 64 + r] = s;
    }
    const float* clsr = img + (size_t)b * NR * EMB + z * 256;
    float* So = g_S + ((pair * 2 + z) * 32) * 64;
    for (int t = wq; t < 32; t += 8) {
        const float* sp = g_selcap + ((size_t)i * 32 + t) * EMB + z * 256;
        float s = 0.f;
        for (int c = ln; c < 256; c += 32) s += sp[c] * clsr[c];
        for (int o = 16; o; o >>= 1) s += __shfl_down_sync(0xffffffffu, s, o);
        if (ln == 0) So[t * 64 + 59] = s;
    }
    {
        int mt2 = wq >> 2, ng2 = wq & 3;
        float sacc[2][4];
#pragma unroll
        for (int t = 0; t < 2; ++t) { sacc[t][0] = sacc[t][1] = sacc[t][2] = sacc[t][3] = 0.f; }
        int mrow = mt2 * 16 + (ln >> 2);
        const float* scap = g_selcap + (size_t)i * 32 * EMB + z * 256;
        for (int kc = 0; kc < 32; ++kc) {
            int k0 = kc * 8 + (ln & 3);
            unsigned a0 = __float_as_uint(scap[(size_t)mrow * EMB + k0]);
            unsigned a1 = __float_as_uint(scap[(size_t)(mrow + 8) * EMB + k0]);
            unsigned a2 = __float_as_uint(scap[(size_t)mrow * EMB + k0 + 4]);
            unsigned a3 = __float_as_uint(scap[(size_t)(mrow + 8) * EMB + k0 + 4]);
#pragma unroll
            for (int nt = 0; nt < 2; ++nt) {
                int tok = ng2 * 16 + nt * 8 + (ln >> 2);
                unsigned b0 = __float_as_uint(R[tok * XSS + k0]);
                unsigned b1 = __float_as_uint(R[tok * XSS + k0 + 4]);
                mma8(sacc[nt], a0, a1, a2, a3, b0, b1);
            }
        }
        int t0 = mt2 * 16 + (ln >> 2);
#pragma unroll
        for (int nt = 0; nt < 2; ++nt) {
            int col = ng2 * 16 + nt * 8 + 2 * (ln & 3);
            if (col < 59)     So[t0 * 64 + col] = sacc[nt][0];
            if (col + 1 < 59) So[t0 * 64 + col + 1] = sacc[nt][1];
            if (col < 59)     So[(t0 + 8) * 64 + col] = sacc[nt][2];
            if (col + 1 < 59) So[(t0 + 8) * 64 + col + 1] = sacc[nt][3];
        }
    }
}

// ---------------- K6 ----------------
__global__ void __launch_bounds__(64) k6_fin(float* __restrict__ out) {
    __shared__ float rinv[64];
    __shared__ float wacc[2];
    int i = blockIdx.x, b = blockIdx.y, tid = threadIdx.x;
    int wq = tid >> 5, ln = tid & 31;
    size_t pair = (size_t)i * BV + b;
    const float* Sa = g_S + pair * 2 * 2048;
    const float* Sb = Sa + 2048;
    const float* Na = g_N2 + pair * 128;
    if (tid < 59) {
        float n2 = Na[tid] + Na[64 + tid];
        rinv[tid] = 1.f / fmaxf(sqrtf(fmaxf(n2, 0.f)), 1e-12f);
    }
    if (tid < 2) wacc[tid] = 0.f;
    __syncthreads();
    int T = g_nt[i];
    float cinv = g_inv[b * NR];
    float acc = 0.f;
    for (int t = wq; t < T; t += 2) {
        float val;
        {
            int col = (ln == 0) ? 59 : ln - 1;
            float s = Sa[t * 64 + col] + Sb[t * 64 + col];
            val = (ln == 0) ? s * cinv : s * rinv[ln - 1];
        }
        if (ln < 28) {
            int col = ln + 31;
            float s = Sa[t * 64 + col] + Sb[t * 64 + col];
            val = fmaxf(val, s * rinv[col]);
        }
        for (int o = 16; o; o >>= 1) val = fmaxf(val, __shfl_xor_sync(0xffffffffu, val, o));
        if (ln == 0) acc += val;
    }
    if (ln == 0) wacc[wq] = acc;
    __syncthreads();
    if (tid == 0) out[b * BT + i] = (wacc[0] + wacc[1]) / (float)T;
}

extern "C" void kernel_launch(void* const* d_in, const int* in_sizes, int n_in,
                              void* d_out, int out_size) {
    const float* img   = (const float*)d_in[0];
    const float* cap   = (const float*)d_in[1];
    const int*   lens  = (const int*)d_in[2];
    const float* talng = (const float*)d_in[3];
    const float* talnb = (const float*)d_in[4];
    const float* taw1  = (const float*)d_in[5];
    const float* tab1  = (const float*)d_in[6];
    const float* taw2  = (const float*)d_in[7];
    const float* tab2  = (const float*)d_in[8];
    const float* tasc  = (const float*)d_in[9];
    const float* calng = (const float*)d_in[10];
    const float* calnb = (const float*)d_in[11];
    const float* caw1  = (const float*)d_in[12];
    const float* cab1  = (const float*)d_in[13];
    const float* casc  = (const float*)d_in[14];
    const float* fw    = (const float*)d_in[15];
    const float* fb    = (const float*)d_in[16];
    float* out = (float*)d_out;

    cudaFuncSetAttribute(k2_logits, cudaFuncAttributeMaxDynamicSharedMemorySize, 208896);
    cudaFuncSetAttribute(k3a,       cudaFuncAttributeMaxDynamicSharedMemorySize, 208896);
    cudaFuncSetAttribute(k3b,       cudaFuncAttributeMaxDynamicSharedMemorySize, 61696);
    cudaFuncSetAttribute(k4_score,  cudaFuncAttributeMaxDynamicSharedMemorySize, 196736);
    cudaFuncSetAttribute(k5d,       cudaFuncAttributeMaxDynamicSharedMemorySize, 67584);

    k0r<<<1024, 256>>>(img);
    k1_img<<<BV, 256>>>(img);
    k2_logits<<<392, 256, 208896>>>(img, talng, talnb, taw1, tab1, taw2, tab2);
    k3a<<<dim3(BT, 8), 256, 208896>>>(cap, lens, calng, calnb, caw1, cab1, fw, fb);
    k3b<<<BT, 256, 61696>>>(cap, lens, casc);
    k4_score<<<BV, 256, 196736>>>(img);
    kw_sel<<<dim3(BT, BV), 256>>>(tasc);
    k5d<<<dim3(BT, BV, 2), 256, 67584>>>(img);
    k6_fin<<<dim3(BT, BV), 64>>>(out);
}